// round 10
// baseline (speedup 1.0000x reference)
#include <cuda_runtime.h>
#include <cstdint>

// Problem constants (fixed by the reference)
#define NUM_B     16
#define NUM_N     2048
#define NUM_Q     (NUM_B * NUM_N)     // 32768 queries
#define M_ANCH    8192
#define NPAIRS    (M_ANCH / 2)        // 4096 anchor pairs
#define BLOCK     128
#define QPT       4                   // queries per thread (register tile)
#define QPB       (BLOCK * QPT)       // 512 queries per CTA-tile
#define S_SPLIT   32                  // anchor splits per query group
#define PAIRS_PER_SPLIT (NPAIRS / S_SPLIT) // 128 pairs = 256 anchors
#define NQGROUP   (NUM_Q / QPB)       // 64 query groups
#define NTILES    (NQGROUP * S_SPLIT) // 2048 work tiles
#define GRID_CTAS (148 * 6)           // persistent grid (1 wave at occ 6)

// Packed (score,index) winners. Encoding guarantees 0 < any real entry, so the
// blend path re-zeroing after use re-arms the buffer for the next graph replay.
__device__ unsigned long long g_best[NUM_Q];   // zero-initialized at load
__device__ int g_done[NQGROUP];                // split-arrival counters, zero-init
__device__ int g_tile_ctr;                     // work-stealing counter, zero-init
__device__ int g_exit_ctr;                     // exit counter, zero-init

// ---------- packed f32x2 helpers (sm_103a) ----------
__device__ __forceinline__ unsigned long long f2pk(float lo, float hi) {
    unsigned long long r;
    asm("mov.b64 %0, {%1, %2};" : "=l"(r) : "f"(lo), "f"(hi));
    return r;
}
__device__ __forceinline__ void f2upk(unsigned long long v, float& lo, float& hi) {
    asm("mov.b64 {%0, %1}, %2;" : "=f"(lo), "=f"(hi) : "l"(v));
}
__device__ __forceinline__ unsigned long long ffma2(unsigned long long a,
                                                    unsigned long long b,
                                                    unsigned long long c) {
    unsigned long long d;
    asm("fma.rn.f32x2 %0, %1, %2, %3;" : "=l"(d) : "l"(a), "l"(b), "l"(c));
    return d;
}

// Monotonic fp32 -> u32 (order-preserving)
__device__ __forceinline__ unsigned int fmono(float f) {
    unsigned int b = __float_as_uint(f);
    return (b & 0x80000000u) ? ~b : (b | 0x80000000u);
}

// Persistent kernel: CTAs steal (qgroup, split) tiles. Tile = 512 queries x
// 128 anchor-pairs. Combine via atomicMax; last split of a group blends.
__global__ __launch_bounds__(BLOCK, 6)
void nn_persistent_kernel(const float* __restrict__ x_start,
                          const float* __restrict__ anchors,
                          const float* __restrict__ sqrt_ac,
                          const float* __restrict__ sqrt_om_ac,
                          const int*   __restrict__ t,
                          float*       __restrict__ out) {
    __shared__ __align__(16) ulonglong2 s01[PAIRS_PER_SPLIT];
    __shared__ __align__(16) ulonglong2 s23[PAIRS_PER_SPLIT];
    __shared__ __align__(16) ulonglong2 s45[PAIRS_PER_SPLIT];
    __shared__ __align__(16) ulonglong2 s67[PAIRS_PER_SPLIT];
    __shared__ __align__(16) unsigned long long snrm[PAIRS_PER_SPLIT];
    __shared__ int s_tile;
    __shared__ int s_old;

    const int tid = threadIdx.x;
    const float4* a4 = reinterpret_cast<const float4*>(anchors);
    const float4* x4 = reinterpret_cast<const float4*>(x_start);

    for (;;) {
        __syncthreads();   // protect s_tile / smem against previous iteration
        if (tid == 0) s_tile = atomicAdd(&g_tile_ctr, 1);
        __syncthreads();
        const int tile = s_tile;
        if (tile >= NTILES) break;

        const int qgroup = tile >> 5;          // tile / S_SPLIT
        const int split  = tile & (S_SPLIT - 1);
        const int q0     = qgroup * QPB + tid * QPT;
        const int pair_base = split * PAIRS_PER_SPLIT;

        // Cooperative smem fill (pair-packed SoA, broadcast-friendly rows)
        for (int j = tid; j < PAIRS_PER_SPLIT; j += BLOCK) {
            const int a0 = (pair_base + j) * 2;
            float4 p0 = a4[a0 * 2];
            float4 p1 = a4[a0 * 2 + 1];
            float4 r0 = a4[a0 * 2 + 2];
            float4 r1 = a4[a0 * 2 + 3];
            float n0 = p0.x * p0.x + p0.y * p0.y + p0.z * p0.z + p0.w * p0.w
                     + p1.x * p1.x + p1.y * p1.y + p1.z * p1.z + p1.w * p1.w;
            float n1 = r0.x * r0.x + r0.y * r0.y + r0.z * r0.z + r0.w * r0.w
                     + r1.x * r1.x + r1.y * r1.y + r1.z * r1.z + r1.w * r1.w;
            s01[j] = make_ulonglong2(f2pk(p0.x, r0.x), f2pk(p0.y, r0.y));
            s23[j] = make_ulonglong2(f2pk(p0.z, r0.z), f2pk(p0.w, r0.w));
            s45[j] = make_ulonglong2(f2pk(p1.x, r1.x), f2pk(p1.y, r1.y));
            s67[j] = make_ulonglong2(f2pk(p1.z, r1.z), f2pk(p1.w, r1.w));
            snrm[j] = f2pk(-0.5f * n0, -0.5f * n1);
        }

        // Load 4 queries, duplicate-packed: xx[k][d] = {x_k[d], x_k[d]}
        unsigned long long xx[QPT][8];
        #pragma unroll
        for (int k = 0; k < QPT; k++) {
            float4 v0 = x4[2 * (q0 + k)];
            float4 v1 = x4[2 * (q0 + k) + 1];
            xx[k][0] = f2pk(v0.x, v0.x);
            xx[k][1] = f2pk(v0.y, v0.y);
            xx[k][2] = f2pk(v0.z, v0.z);
            xx[k][3] = f2pk(v0.w, v0.w);
            xx[k][4] = f2pk(v1.x, v1.x);
            xx[k][5] = f2pk(v1.y, v1.y);
            xx[k][6] = f2pk(v1.z, v1.z);
            xx[k][7] = f2pk(v1.w, v1.w);
        }

        float best[QPT];
        int   bi[QPT];
        #pragma unroll
        for (int k = 0; k < QPT; k++) { best[k] = -3.402823466e38f; bi[k] = 0; }

        __syncthreads();

        #pragma unroll 2
        for (int j = 0; j < PAIRS_PER_SPLIT; j++) {
            ulonglong2 a01 = s01[j];
            ulonglong2 a23 = s23[j];
            ulonglong2 a45 = s45[j];
            ulonglong2 a67 = s67[j];
            unsigned long long nr = snrm[j];

            unsigned long long acc[QPT];
            #pragma unroll
            for (int k = 0; k < QPT; k++) acc[k] = nr;
            #pragma unroll
            for (int k = 0; k < QPT; k++) acc[k] = ffma2(xx[k][0], a01.x, acc[k]);
            #pragma unroll
            for (int k = 0; k < QPT; k++) acc[k] = ffma2(xx[k][1], a01.y, acc[k]);
            #pragma unroll
            for (int k = 0; k < QPT; k++) acc[k] = ffma2(xx[k][2], a23.x, acc[k]);
            #pragma unroll
            for (int k = 0; k < QPT; k++) acc[k] = ffma2(xx[k][3], a23.y, acc[k]);
            #pragma unroll
            for (int k = 0; k < QPT; k++) acc[k] = ffma2(xx[k][4], a45.x, acc[k]);
            #pragma unroll
            for (int k = 0; k < QPT; k++) acc[k] = ffma2(xx[k][5], a45.y, acc[k]);
            #pragma unroll
            for (int k = 0; k < QPT; k++) acc[k] = ffma2(xx[k][6], a67.x, acc[k]);
            #pragma unroll
            for (int k = 0; k < QPT; k++) acc[k] = ffma2(xx[k][7], a67.y, acc[k]);

            const int ia = (pair_base + j) * 2;
            #pragma unroll
            for (int k = 0; k < QPT; k++) {
                float sc0, sc1;
                f2upk(acc[k], sc0, sc1);
                // Pair-max, then single predicated update.
                // Ties: sc1==sc0 -> lower index; m==best -> keep earlier index.
                float m  = fmaxf(sc0, sc1);
                int   ii = ia + (sc1 > sc0 ? 1 : 0);
                bool  up = m > best[k];
                best[k] = up ? m  : best[k];
                bi[k]   = up ? ii : bi[k];
            }
        }

        // Deterministic global combine: max on (mono(score), ~idx) packed u64.
        #pragma unroll
        for (int k = 0; k < QPT; k++) {
            unsigned long long pk =
                (((unsigned long long)fmono(best[k])) << 32) |
                (unsigned long long)(0xFFFFFFFFu - (unsigned int)bi[k]);
            atomicMax(&g_best[q0 + k], pk);
        }

        // Split-k semaphore: last tile of this query group does the blend.
        __threadfence();                   // release: my atomicMax visible gpu-wide
        __syncthreads();
        if (tid == 0) s_old = atomicAdd(&g_done[qgroup], 1);
        __syncthreads();

        if (s_old == S_SPLIT - 1) {
            __threadfence();               // acquire: see all splits' atomicMax
            if (tid == 0) g_done[qgroup] = 0;   // re-arm for next replay

            const int b  = q0 >> 11;       // all 4 queries share the same batch
            const int tt = __ldg(&t[b]);
            const float sa = __ldg(&sqrt_ac[tt]);
            const float sb = __ldg(&sqrt_om_ac[tt]);

            float4* out4 = reinterpret_cast<float4*>(out);
            #pragma unroll
            for (int k = 0; k < QPT; k++) {
                const int q = q0 + k;
                unsigned long long pk = __ldcg(&g_best[q]);
                const int widx = (int)(0xFFFFFFFFu - (unsigned int)pk);
                __stcg(&g_best[q], 0ull);  // re-arm winner slot for next replay

                float4 xv0 = x4[2 * q];
                float4 xv1 = x4[2 * q + 1];
                float4 m0  = a4[2 * widx];
                float4 m1  = a4[2 * widx + 1];

                float4 o0, o1;
                o0.x = sa * xv0.x + sb * m0.x;
                o0.y = sa * xv0.y + sb * m0.y;
                o0.z = sa * xv0.z + sb * m0.z;
                o0.w = sa * xv0.w + sb * m0.w;
                o1.x = sa * xv1.x + sb * m1.x;
                o1.y = sa * xv1.y + sb * m1.y;
                o1.z = sa * xv1.z + sb * m1.z;
                o1.w = sa * xv1.w + sb * m1.w;

                out4[2 * q]     = o0;
                out4[2 * q + 1] = o1;
            }
        }
    }

    // Re-arm work-stealing counters for the next graph replay. Only the LAST
    // exiting CTA resets (no mid-run decrements => no tile double-grab).
    if (tid == 0) {
        __threadfence();
        int e = atomicAdd(&g_exit_ctr, 1);
        if (e == GRID_CTAS - 1) {
            g_tile_ctr = 0;
            g_exit_ctr = 0;
            __threadfence();
        }
    }
}

extern "C" void kernel_launch(void* const* d_in, const int* in_sizes, int n_in,
                              void* d_out, int out_size) {
    const float* x_start   = (const float*)d_in[0];   // [16,2048,4,2]
    const float* anchors   = (const float*)d_in[1];   // [8192,4,2]
    const float* sqrt_ac   = (const float*)d_in[2];   // [1000]
    const float* sqrt_omac = (const float*)d_in[3];   // [1000]
    const int*   t         = (const int*)d_in[4];     // [16]
    float*       out       = (float*)d_out;           // [16,2048,4,2]

    (void)in_sizes; (void)n_in; (void)out_size;

    nn_persistent_kernel<<<GRID_CTAS, BLOCK>>>(x_start, anchors, sqrt_ac,
                                               sqrt_omac, t, out);
}

// round 11
// speedup vs baseline: 1.1447x; 1.1447x over previous
#include <cuda_runtime.h>
#include <cstdint>

// Problem constants (fixed by the reference)
#define NUM_B     16
#define NUM_N     2048
#define NUM_Q     (NUM_B * NUM_N)     // 32768 queries
#define M_ANCH    8192
#define NPAIRS    (M_ANCH / 2)        // 4096 anchor pairs
#define BLOCK     128
#define QPT       4                   // queries per thread (register tile)
#define QPB       (BLOCK * QPT)       // 512 queries per CTA
#define S_SPLIT   16                  // anchor splits (blockIdx.y)
#define PAIRS_PER_SPLIT (NPAIRS / S_SPLIT) // 256 pairs = 512 anchors
#define NQGROUP   (NUM_Q / QPB)       // 64 query groups

// Packed (score,index) winners. Encoding guarantees 0 < any real entry, so the
// blend path re-zeroing after use re-arms the buffer for the next graph replay.
__device__ unsigned long long g_best[NUM_Q];   // zero-initialized at load
__device__ int g_done[NQGROUP];                // split-arrival counters, zero-init

// ---------- packed f32x2 helpers (sm_103a) ----------
__device__ __forceinline__ unsigned long long f2pk(float lo, float hi) {
    unsigned long long r;
    asm("mov.b64 %0, {%1, %2};" : "=l"(r) : "f"(lo), "f"(hi));
    return r;
}
__device__ __forceinline__ void f2upk(unsigned long long v, float& lo, float& hi) {
    asm("mov.b64 {%0, %1}, %2;" : "=f"(lo), "=f"(hi) : "l"(v));
}
__device__ __forceinline__ unsigned long long ffma2(unsigned long long a,
                                                    unsigned long long b,
                                                    unsigned long long c) {
    unsigned long long d;
    asm("fma.rn.f32x2 %0, %1, %2, %3;" : "=l"(d) : "l"(a), "l"(b), "l"(c));
    return d;
}

// Monotonic fp32 -> u32 (order-preserving)
__device__ __forceinline__ unsigned int fmono(float f) {
    unsigned int b = __float_as_uint(f);
    return (b & 0x80000000u) ? ~b : (b | 0x80000000u);
}

// Fused kernel: CTA = 512 queries x 256 anchor-pairs. After the scan, CTAs
// combine via atomicMax; the last-arriving CTA of each query group blends.
__global__ __launch_bounds__(BLOCK, 4)
void nn_fused_kernel(const float* __restrict__ x_start,
                     const float* __restrict__ anchors,
                     const float* __restrict__ sqrt_ac,
                     const float* __restrict__ sqrt_om_ac,
                     const int*   __restrict__ t,
                     float*       __restrict__ out) {
    __shared__ __align__(16) ulonglong2 s01[PAIRS_PER_SPLIT];
    __shared__ __align__(16) ulonglong2 s23[PAIRS_PER_SPLIT];
    __shared__ __align__(16) ulonglong2 s45[PAIRS_PER_SPLIT];
    __shared__ __align__(16) ulonglong2 s67[PAIRS_PER_SPLIT];
    __shared__ __align__(16) unsigned long long snrm[PAIRS_PER_SPLIT];
    __shared__ int s_old;

    const int tid   = threadIdx.x;
    const int split = blockIdx.y;
    const int q0    = blockIdx.x * QPB + tid * QPT;   // 4 consecutive queries
    const int pair_base = split * PAIRS_PER_SPLIT;

    const float4* a4 = reinterpret_cast<const float4*>(anchors);
    const float4* x4 = reinterpret_cast<const float4*>(x_start);

    // Cooperative smem fill (pair-packed SoA, broadcast-friendly rows)
    for (int j = tid; j < PAIRS_PER_SPLIT; j += BLOCK) {
        const int a0 = (pair_base + j) * 2;
        float4 p0 = a4[a0 * 2];
        float4 p1 = a4[a0 * 2 + 1];
        float4 r0 = a4[a0 * 2 + 2];
        float4 r1 = a4[a0 * 2 + 3];
        float n0 = p0.x * p0.x + p0.y * p0.y + p0.z * p0.z + p0.w * p0.w
                 + p1.x * p1.x + p1.y * p1.y + p1.z * p1.z + p1.w * p1.w;
        float n1 = r0.x * r0.x + r0.y * r0.y + r0.z * r0.z + r0.w * r0.w
                 + r1.x * r1.x + r1.y * r1.y + r1.z * r1.z + r1.w * r1.w;
        s01[j] = make_ulonglong2(f2pk(p0.x, r0.x), f2pk(p0.y, r0.y));
        s23[j] = make_ulonglong2(f2pk(p0.z, r0.z), f2pk(p0.w, r0.w));
        s45[j] = make_ulonglong2(f2pk(p1.x, r1.x), f2pk(p1.y, r1.y));
        s67[j] = make_ulonglong2(f2pk(p1.z, r1.z), f2pk(p1.w, r1.w));
        snrm[j] = f2pk(-0.5f * n0, -0.5f * n1);
    }

    // Load 4 queries, duplicate-packed: xx[k][d] = {x_k[d], x_k[d]}
    unsigned long long xx[QPT][8];
    #pragma unroll
    for (int k = 0; k < QPT; k++) {
        float4 v0 = x4[2 * (q0 + k)];
        float4 v1 = x4[2 * (q0 + k) + 1];
        xx[k][0] = f2pk(v0.x, v0.x);
        xx[k][1] = f2pk(v0.y, v0.y);
        xx[k][2] = f2pk(v0.z, v0.z);
        xx[k][3] = f2pk(v0.w, v0.w);
        xx[k][4] = f2pk(v1.x, v1.x);
        xx[k][5] = f2pk(v1.y, v1.y);
        xx[k][6] = f2pk(v1.z, v1.z);
        xx[k][7] = f2pk(v1.w, v1.w);
    }

    float best[QPT];
    int   bi[QPT];
    #pragma unroll
    for (int k = 0; k < QPT; k++) { best[k] = -3.402823466e38f; bi[k] = 0; }

    __syncthreads();

    #pragma unroll 4
    for (int j = 0; j < PAIRS_PER_SPLIT; j++) {
        ulonglong2 a01 = s01[j];
        ulonglong2 a23 = s23[j];
        ulonglong2 a45 = s45[j];
        ulonglong2 a67 = s67[j];
        unsigned long long nr = snrm[j];

        unsigned long long acc[QPT];
        #pragma unroll
        for (int k = 0; k < QPT; k++) acc[k] = nr;
        #pragma unroll
        for (int k = 0; k < QPT; k++) acc[k] = ffma2(xx[k][0], a01.x, acc[k]);
        #pragma unroll
        for (int k = 0; k < QPT; k++) acc[k] = ffma2(xx[k][1], a01.y, acc[k]);
        #pragma unroll
        for (int k = 0; k < QPT; k++) acc[k] = ffma2(xx[k][2], a23.x, acc[k]);
        #pragma unroll
        for (int k = 0; k < QPT; k++) acc[k] = ffma2(xx[k][3], a23.y, acc[k]);
        #pragma unroll
        for (int k = 0; k < QPT; k++) acc[k] = ffma2(xx[k][4], a45.x, acc[k]);
        #pragma unroll
        for (int k = 0; k < QPT; k++) acc[k] = ffma2(xx[k][5], a45.y, acc[k]);
        #pragma unroll
        for (int k = 0; k < QPT; k++) acc[k] = ffma2(xx[k][6], a67.x, acc[k]);
        #pragma unroll
        for (int k = 0; k < QPT; k++) acc[k] = ffma2(xx[k][7], a67.y, acc[k]);

        const int ia = (pair_base + j) * 2;
        #pragma unroll
        for (int k = 0; k < QPT; k++) {
            float sc0, sc1;
            f2upk(acc[k], sc0, sc1);
            // Pair-max first, then single predicated update.
            // Ties: sc1==sc0 -> lower index; m==best -> keep earlier index.
            float m  = fmaxf(sc0, sc1);
            int   ii = ia + (sc1 > sc0 ? 1 : 0);
            bool  up = m > best[k];
            best[k] = up ? m  : best[k];
            bi[k]   = up ? ii : bi[k];
        }
    }

    // Deterministic global combine: max on (mono(score), ~idx) packed u64.
    // Higher score wins; equal score -> larger (0xFFFFFFFF - idx) = smaller idx.
    #pragma unroll
    for (int k = 0; k < QPT; k++) {
        unsigned long long pk =
            (((unsigned long long)fmono(best[k])) << 32) |
            (unsigned long long)(0xFFFFFFFFu - (unsigned int)bi[k]);
        atomicMax(&g_best[q0 + k], pk);
    }

    // Split-k semaphore: last CTA to finish this query group does the blend.
    __threadfence();                       // release: my atomicMax visible gpu-wide
    __syncthreads();
    if (tid == 0) s_old = atomicAdd(&g_done[blockIdx.x], 1);
    __syncthreads();

    if (s_old == S_SPLIT - 1) {
        __threadfence();                   // acquire: see all splits' atomicMax
        if (tid == 0) g_done[blockIdx.x] = 0;   // re-arm counter for next replay

        const int b  = q0 >> 11;           // all 4 queries share the same batch
        const int tt = __ldg(&t[b]);
        const float sa = __ldg(&sqrt_ac[tt]);
        const float sb = __ldg(&sqrt_om_ac[tt]);

        float4* out4 = reinterpret_cast<float4*>(out);
        #pragma unroll
        for (int k = 0; k < QPT; k++) {
            const int q = q0 + k;
            unsigned long long pk = __ldcg(&g_best[q]);   // L2 read (atomics live at L2)
            const int widx = (int)(0xFFFFFFFFu - (unsigned int)pk);
            __stcg(&g_best[q], 0ull);      // re-arm winner slot for next replay

            float4 xv0 = x4[2 * q];
            float4 xv1 = x4[2 * q + 1];
            float4 m0  = a4[2 * widx];
            float4 m1  = a4[2 * widx + 1];

            float4 o0, o1;
            o0.x = sa * xv0.x + sb * m0.x;
            o0.y = sa * xv0.y + sb * m0.y;
            o0.z = sa * xv0.z + sb * m0.z;
            o0.w = sa * xv0.w + sb * m0.w;
            o1.x = sa * xv1.x + sb * m1.x;
            o1.y = sa * xv1.y + sb * m1.y;
            o1.z = sa * xv1.z + sb * m1.z;
            o1.w = sa * xv1.w + sb * m1.w;

            out4[2 * q]     = o0;
            out4[2 * q + 1] = o1;
        }
    }
}

extern "C" void kernel_launch(void* const* d_in, const int* in_sizes, int n_in,
                              void* d_out, int out_size) {
    const float* x_start   = (const float*)d_in[0];   // [16,2048,4,2]
    const float* anchors   = (const float*)d_in[1];   // [8192,4,2]
    const float* sqrt_ac   = (const float*)d_in[2];   // [1000]
    const float* sqrt_omac = (const float*)d_in[3];   // [1000]
    const int*   t         = (const int*)d_in[4];     // [16]
    float*       out       = (float*)d_out;           // [16,2048,4,2]

    (void)in_sizes; (void)n_in; (void)out_size;

    dim3 grid(NQGROUP, S_SPLIT);   // 64 x 16 = 1024 CTAs
    nn_fused_kernel<<<grid, BLOCK>>>(x_start, anchors, sqrt_ac,
                                     sqrt_omac, t, out);
}